// round 12
// baseline (speedup 1.0000x reference)
#include <cuda_runtime.h>
#include <stdint.h>

#define NN2  361
#define MM   361
#define NT   384
#define HMASK 1023
#define MAXG  64
#define MAXST 256

__device__ __forceinline__ unsigned hash_fn(int v) {
    return (((unsigned)v) * 2654435761u) >> 22;
}

__device__ __forceinline__ void hins(int* hset, int v) {
    unsigned h = hash_fn(v) & HMASK;
    while (true) {
        int prev = atomicCAS(&hset[h], -1, v);
        if (prev == -1 || prev == v) break;
        h = (h + 1) & HMASK;
    }
}

__device__ __forceinline__ bool hprobe(const int* hset, int v) {
    unsigned h = hash_fn(v) & HMASK;
    while (true) {
        int s = hset[h];
        if (s == -1) return false;
        if (s == v)  return true;
        h = (h + 1) & HMASK;
    }
}

__global__ __launch_bounds__(NT, 4)
void superko_kernel(const int* __restrict__ ZposT,
                    const int* __restrict__ current_player,
                    const int* __restrict__ current_hash,
                    const int* __restrict__ hash_history,
                    const int* __restrict__ move_count,
                    const int* __restrict__ legal,
                    const int* __restrict__ sidx,
                    const int* __restrict__ sptr,
                    const int* __restrict__ gptr,
                    const int* __restrict__ cap,
                    float* __restrict__ out, int B)
{
    __shared__ int hset0[1024];
    __shared__ int hset1[1024];
    __shared__ int gx0[MAXG];
    __shared__ int gx1[MAXG];
    __shared__ int sdelta[MAXST];   // general-CSR fallback scratch
    __shared__ int sflag;           // bit0: b0 uniform, bit1: b1 uniform

    const int tid = threadIdx.x;
    const int b0  = blockIdx.x * 2;
    const int b1  = b0 + 1;
    const bool hasB1 = (b1 < B);

    // ---------------- phase 0: fire ALL loads for BOTH boards ----------------
    const int p0 = __ldg(&current_player[b0]);
    int mc0      = __ldg(&move_count[b0]);
    const int ch0 = __ldg(&current_hash[b0]);
    if (mc0 > MM) mc0 = MM;
    if (mc0 < 0)  mc0 = 0;

    int p1 = 0, mc1 = 0, ch1 = 0;
    if (hasB1) {
        p1  = __ldg(&current_player[b1]);
        mc1 = __ldg(&move_count[b1]);
        ch1 = __ldg(&current_hash[b1]);
        if (mc1 > MM) mc1 = MM;
        if (mc1 < 0)  mc1 = 0;
    }

    const bool hasc = (tid < NN2);

    // board-independent zobrist cell values (shared by both boards!)
    int ze = 0, zb = 0, zw = 0;
    int4 c4_0 = make_int4(-1, -1, -1, -1), c4_1 = make_int4(-1, -1, -1, -1);
    int lg0 = 0, lg1 = 0, hv0 = 0, hv1 = 0;
    if (hasc) {
        ze = __ldg(&ZposT[tid]);
        zb = __ldg(&ZposT[NN2 + tid]);
        zw = __ldg(&ZposT[2 * NN2 + tid]);
        c4_0 = ((const int4*)(cap + (long long)b0 * NN2 * 4))[tid];
        lg0  = legal[(long long)b0 * NN2 + tid];
        hv0  = hash_history[(long long)b0 * MM + tid];
        if (hasB1) {
            c4_1 = ((const int4*)(cap + (long long)b1 * NN2 * 4))[tid];
            lg1  = legal[(long long)b1 * NN2 + tid];
            hv1  = hash_history[(long long)b1 * MM + tid];
        }
    }

    // CSR scalars, both boards
    const int gs0 = gptr[b0];
    int ng0 = gptr[b0 + 1] - gs0;
    if (ng0 < 0) ng0 = 0;
    if (ng0 > MAXG) ng0 = MAXG;
    const int sb0 = sptr[gs0];
    int nst0 = sptr[gs0 + ng0] - sb0;
    if (nst0 < 0) nst0 = 0;
    if (nst0 > MAXST) nst0 = MAXST;

    int gs1 = 0, ng1 = 0, sb1 = 0, nst1 = 0;
    if (hasB1) {
        gs1 = gptr[b1];
        ng1 = gptr[b1 + 1] - gs1;
        if (ng1 < 0) ng1 = 0;
        if (ng1 > MAXG) ng1 = MAXG;
        sb1 = sptr[gs1];
        nst1 = sptr[gs1 + ng1] - sb1;
        if (nst1 < 0) nst1 = 0;
        if (nst1 > MAXST) nst1 = MAXST;
    }

    // stone removal deltas (opponent color), both boards
    int sd0 = 0, sd1 = 0;
    if (tid < nst0) {
        int c = sidx[sb0 + tid];
        sd0 = __ldg(&ZposT[c]) ^ ((p0 == 0) ? __ldg(&ZposT[2 * NN2 + c])
                                            : __ldg(&ZposT[NN2 + c]));
    }
    if (tid < nst1) {
        int c = sidx[sb1 + tid];
        sd1 = __ldg(&ZposT[c]) ^ ((p1 == 0) ? __ldg(&ZposT[2 * NN2 + c])
                                            : __ldg(&ZposT[NN2 + c]));
    }

    // warp 0: parallel uniform-CSR verify for both boards
    if (tid < 32) {
        bool ok0 = true, ok1 = true;
        if (tid == 0)
            ok0 = (nst0 == ng0 * 16) && ((nst0 & 31) == 0) && (ng0 <= 31);
        else if (tid <= ng0 && ng0 <= 31)
            ok0 = (sptr[gs0 + tid] == sb0 + 16 * tid);
        if (hasB1) {
            if (tid == 0)
                ok1 = (nst1 == ng1 * 16) && ((nst1 & 31) == 0) && (ng1 <= 31);
            else if (tid <= ng1 && ng1 <= 31)
                ok1 = (sptr[gs1 + tid] == sb1 + 16 * tid);
        }
        unsigned m0 = __ballot_sync(0xffffffffu, ok0);
        unsigned m1 = __ballot_sync(0xffffffffu, ok1);
        if (tid == 0)
            sflag = ((m0 == 0xffffffffu) ? 1 : 0) | ((m1 == 0xffffffffu) ? 2 : 0);
    }

    // init both hash sets: 512 STS.128 total across 384 threads
    if (tid < 256) ((int4*)hset0)[tid] = make_int4(-1, -1, -1, -1);
    {
        int t = tid - 128;                       // threads 128..383 -> hset1
        if (t >= 0) ((int4*)hset1)[t] = make_int4(-1, -1, -1, -1);
    }

    // speculative group XOR (fast path), both boards
    if (tid < nst0) {
        int d = sd0;
        d ^= __shfl_xor_sync(0xffffffffu, d, 8);
        d ^= __shfl_xor_sync(0xffffffffu, d, 4);
        d ^= __shfl_xor_sync(0xffffffffu, d, 2);
        d ^= __shfl_xor_sync(0xffffffffu, d, 1);
        if ((tid & 15) == 0) gx0[tid >> 4] = d;
    }
    if (tid < nst1) {
        int d = sd1;
        d ^= __shfl_xor_sync(0xffffffffu, d, 8);
        d ^= __shfl_xor_sync(0xffffffffu, d, 4);
        d ^= __shfl_xor_sync(0xffffffffu, d, 2);
        d ^= __shfl_xor_sync(0xffffffffu, d, 1);
        if ((tid & 15) == 0) gx1[tid >> 4] = d;
    }

    __syncthreads();   // barrier 1

    // ---------------- phase 1: inserts for both boards ----------------
    if (tid < mc0) hins(hset0, hv0);
    if (tid < mc1) hins(hset1, hv1);

    // general-CSR fallbacks (block-uniform flags; never taken on this dataset)
    if (!(sflag & 1)) {
        if (tid < nst0) sdelta[tid] = sd0;
        __syncthreads();
        if (tid < ng0) {
            int s0 = sptr[gs0 + tid] - sb0;
            int s1 = sptr[gs0 + tid + 1] - sb0;
            if (s0 < 0) s0 = 0;
            if (s1 > nst0) s1 = nst0;
            int x = 0;
            for (int s = s0; s < s1; ++s) x ^= sdelta[s];
            gx0[tid] = x;
        }
        __syncthreads();
    }
    if (!(sflag & 2) && hasB1) {
        if (tid < nst1) sdelta[tid] = sd1;
        __syncthreads();
        if (tid < ng1) {
            int s0 = sptr[gs1 + tid] - sb1;
            int s1 = sptr[gs1 + tid + 1] - sb1;
            if (s0 < 0) s0 = 0;
            if (s1 > nst1) s1 = nst1;
            int x = 0;
            for (int s = s0; s < s1; ++s) x ^= sdelta[s];
            gx1[tid] = x;
        }
    }

    __syncthreads();   // barrier 2

    // ---------------- phase 2: probes + outputs ----------------
    if (hasc) {
        {
            float r = 0.0f;
            if (lg0 != 0) {
                int cd = 0;
                if (c4_0.x >= 0) cd ^= gx0[c4_0.x];
                if (c4_0.y >= 0) cd ^= gx0[c4_0.y];
                if (c4_0.z >= 0) cd ^= gx0[c4_0.z];
                if (c4_0.w >= 0) cd ^= gx0[c4_0.w];
                int cand = ch0 ^ (ze ^ ((p0 == 0) ? zb : zw)) ^ cd;
                r = hprobe(hset0, cand) ? 0.0f : 1.0f;
            }
            out[(long long)b0 * NN2 + tid] = r;
        }
        if (hasB1) {
            float r = 0.0f;
            if (lg1 != 0) {
                int cd = 0;
                if (c4_1.x >= 0) cd ^= gx1[c4_1.x];
                if (c4_1.y >= 0) cd ^= gx1[c4_1.y];
                if (c4_1.z >= 0) cd ^= gx1[c4_1.z];
                if (c4_1.w >= 0) cd ^= gx1[c4_1.w];
                int cand = ch1 ^ (ze ^ ((p1 == 0) ? zb : zw)) ^ cd;
                r = hprobe(hset1, cand) ? 0.0f : 1.0f;
            }
            out[(long long)b1 * NN2 + tid] = r;
        }
    }
}

extern "C" void kernel_launch(void* const* d_in, const int* in_sizes, int n_in,
                              void* d_out, int out_size) {
    const int* ZposT        = (const int*)d_in[0];
    const int* cur_player   = (const int*)d_in[1];
    const int* cur_hash     = (const int*)d_in[2];
    const int* hash_hist    = (const int*)d_in[3];
    const int* mv_count     = (const int*)d_in[4];
    const int* lg           = (const int*)d_in[5];
    const int* sidx         = (const int*)d_in[6];
    const int* sptr         = (const int*)d_in[7];
    const int* gptr         = (const int*)d_in[8];
    const int* cap          = (const int*)d_in[9];

    float* out = (float*)d_out;
    const int B = in_sizes[8] - 1;   // gptr has B+1 entries

    superko_kernel<<<(B + 1) / 2, NT>>>(ZposT, cur_player, cur_hash, hash_hist,
                                        mv_count, lg, sidx, sptr, gptr, cap, out, B);
}

// round 13
// speedup vs baseline: 1.2362x; 1.2362x over previous
#include <cuda_runtime.h>
#include <stdint.h>

#define NN2  361
#define MM   361
#define NT   384
#define HSLOTS 2048
#define HMASK  2047
#define MAXG  64
#define MAXST 256

__device__ __forceinline__ unsigned hash_fn(int v) {
    return (((unsigned)v) * 2654435761u) >> 21;   // top 11 bits -> [0,2048)
}

__global__ __launch_bounds__(NT, 4)
void superko_kernel(const int* __restrict__ ZposT,
                    const int* __restrict__ current_player,
                    const int* __restrict__ current_hash,
                    const int* __restrict__ hash_history,
                    const int* __restrict__ move_count,
                    const int* __restrict__ legal,
                    const int* __restrict__ sidx,
                    const int* __restrict__ sptr,
                    const int* __restrict__ gptr,
                    const int* __restrict__ cap,
                    float* __restrict__ out)
{
    __shared__ int hset[HSLOTS];
    __shared__ int gxor[MAXG];
    __shared__ int sdelta[MAXST];   // general-CSR fallback only
    __shared__ int sflag;

    const int b   = blockIdx.x;
    const int tid = threadIdx.x;

    // -------- phase 0: fire all loads --------
    const int player = __ldg(&current_player[b]);
    int mc           = __ldg(&move_count[b]);
    const int ch     = __ldg(&current_hash[b]);
    if (mc > MM) mc = MM;
    if (mc < 0)  mc = 0;

    const bool hasc = (tid < NN2);

    int4 c4 = make_int4(-1, -1, -1, -1);
    int  lgv = 0, ze = 0, zb = 0, zw = 0, hv = 0;
    if (hasc) {
        c4  = ((const int4*)(cap + (long long)b * NN2 * 4))[tid];
        lgv = legal[(long long)b * NN2 + tid];
        ze  = __ldg(&ZposT[tid]);
        zb  = __ldg(&ZposT[NN2 + tid]);
        zw  = __ldg(&ZposT[2 * NN2 + tid]);
        hv  = hash_history[(long long)b * MM + tid];
    }

    // CSR scalars
    const int gstart = gptr[b];
    int ng = gptr[b + 1] - gstart;
    if (ng < 0) ng = 0;
    if (ng > MAXG) ng = MAXG;
    const int sbase = sptr[gstart];
    int nst = sptr[gstart + ng] - sbase;
    if (nst < 0) nst = 0;
    if (nst > MAXST) nst = MAXST;

    // coalesced stone gather + removal delta (opponent color)
    int sd = 0;
    if (tid < nst) {
        int c = sidx[sbase + tid];
        sd = __ldg(&ZposT[c]) ^ ((player == 0) ? __ldg(&ZposT[2 * NN2 + c])
                                               : __ldg(&ZposT[NN2 + c]));
    }

    // warp 0: parallel uniform-CSR verify
    if (tid < 32) {
        bool ok = true;
        if (tid == 0)
            ok = (nst == ng * 16) && ((nst & 31) == 0) && (ng <= 31);
        else if (tid <= ng && ng <= 31)
            ok = (sptr[gstart + tid] == sbase + 16 * tid);
        unsigned m = __ballot_sync(0xffffffffu, ok);
        if (tid == 0) sflag = (m == 0xffffffffu) ? 1 : 0;
    }

    // hset init: 8 KB = 512 STS.128; threads 0..383 do 1, threads 0..127 do a 2nd
    ((int4*)hset)[tid] = make_int4(-1, -1, -1, -1);
    if (tid < HSLOTS / 4 - NT) ((int4*)hset)[NT + tid] = make_int4(-1, -1, -1, -1);

    // speculative group XOR (16-lane butterfly); fallback overwrites if needed
    if (tid < nst) {
        int d = sd;
        d ^= __shfl_xor_sync(0xffffffffu, d, 8);
        d ^= __shfl_xor_sync(0xffffffffu, d, 4);
        d ^= __shfl_xor_sync(0xffffffffu, d, 2);
        d ^= __shfl_xor_sync(0xffffffffu, d, 1);
        if ((tid & 15) == 0) gxor[tid >> 4] = d;
    }

    __syncthreads();   // barrier 1

    // -------- phase 1: insert (load factor 0.18 -> first CAS succeeds ~97%) --------
    if (tid < mc) {
        unsigned h = hash_fn(hv) & HMASK;
        int prev = atomicCAS(&hset[h], -1, hv);
        while (prev != -1 && prev != hv) {
            h = (h + 1) & HMASK;
            prev = atomicCAS(&hset[h], -1, hv);
        }
    }

    if (!sflag) {      // general-CSR fallback (block-uniform)
        if (tid < nst) sdelta[tid] = sd;
        __syncthreads();
        if (tid < ng) {
            int s0 = sptr[gstart + tid] - sbase;
            int s1 = sptr[gstart + tid + 1] - sbase;
            if (s0 < 0) s0 = 0;
            if (s1 > nst) s1 = nst;
            int x = 0;
            for (int s = s0; s < s1; ++s) x ^= sdelta[s];
            gxor[tid] = x;
        }
    }

    __syncthreads();   // barrier 2

    // -------- phase 2: paired branch-light probe + output --------
    if (hasc) {
        float r = 0.0f;
        if (lgv != 0) {
            int cd = 0;
            if (c4.x >= 0) cd ^= gxor[c4.x];
            if (c4.y >= 0) cd ^= gxor[c4.y];
            if (c4.z >= 0) cd ^= gxor[c4.z];
            if (c4.w >= 0) cd ^= gxor[c4.w];
            int cand = ch ^ (ze ^ ((player == 0) ? zb : zw)) ^ cd;

            // paired probe: two independent LDS per iteration, branchless resolve.
            // hash values are XORs of 31-bit ints -> cand >= 0, never the -1 sentinel.
            bool found = false;
            unsigned h = hash_fn(cand) & HMASK;
            while (true) {
                int v0 = hset[h];
                int v1 = hset[(h + 1) & HMASK];
                bool hit  = (v0 == cand) | ((v0 != -1) & (v1 == cand));
                bool done = hit | (v0 == -1) | (v1 == -1);
                if (done) { found = hit; break; }
                h = (h + 2) & HMASK;
            }
            r = found ? 0.0f : 1.0f;
        }
        out[(long long)b * NN2 + tid] = r;
    }
}

extern "C" void kernel_launch(void* const* d_in, const int* in_sizes, int n_in,
                              void* d_out, int out_size) {
    const int* ZposT        = (const int*)d_in[0];
    const int* cur_player   = (const int*)d_in[1];
    const int* cur_hash     = (const int*)d_in[2];
    const int* hash_hist    = (const int*)d_in[3];
    const int* mv_count     = (const int*)d_in[4];
    const int* lg           = (const int*)d_in[5];
    const int* sidx         = (const int*)d_in[6];
    const int* sptr         = (const int*)d_in[7];
    const int* gptr         = (const int*)d_in[8];
    const int* cap          = (const int*)d_in[9];

    float* out = (float*)d_out;
    const int B = in_sizes[8] - 1;   // gptr has B+1 entries

    superko_kernel<<<B, NT>>>(ZposT, cur_player, cur_hash, hash_hist,
                              mv_count, lg, sidx, sptr, gptr, cap, out);
}